// round 1
// baseline (speedup 1.0000x reference)
#include <cuda_runtime.h>

// Problem constants (fixed by reference_code)
#define IN_F   256
#define N_ASS  4096
#define OUT_F  256
#define BATCH  128
#define ASS0   IN_F            // 256   : first associative neuron index
#define OUT0   (IN_F + N_ASS)  // 4352  : first output neuron index

// Scratch (device globals — no runtime allocation allowed)
__device__ float g_W1[IN_F * N_ASS];   // [256][4096]  dense hop-1 weight matrix
__device__ float g_W2[N_ASS * OUT_F];  // [4096][256]  dense hop-2 (output edges only)
__device__ float g_H [BATCH * N_ASS];  // [128][4096]  hidden activations (acc at assoc)

// ---------------------------------------------------------------------------
// Kernel 1: zero W1, W2 and d_out (vectorized grid-stride)
// ---------------------------------------------------------------------------
__global__ void zero_kernel(float* __restrict__ out) {
    const int stride = gridDim.x * blockDim.x;
    int tid = blockIdx.x * blockDim.x + threadIdx.x;

    float4 z = make_float4(0.f, 0.f, 0.f, 0.f);
    float4* w1 = reinterpret_cast<float4*>(g_W1);
    float4* w2 = reinterpret_cast<float4*>(g_W2);
    float4* o4 = reinterpret_cast<float4*>(out);

    const int n1 = (IN_F * N_ASS) / 4;   // 262144
    const int n2 = (N_ASS * OUT_F) / 4;  // 262144
    const int n3 = (BATCH * OUT_F) / 4;  // 8192

    for (int i = tid; i < n1; i += stride) w1[i] = z;
    for (int i = tid; i < n2; i += stride) w2[i] = z;
    for (int i = tid; i < n3; i += stride) o4[i] = z;
}

// ---------------------------------------------------------------------------
// Kernel 2: scatter hop-1 edges into dense W1
// ---------------------------------------------------------------------------
__global__ void scatter1_kernel(const int* __restrict__ src,
                                const int* __restrict__ dst,
                                const float* __restrict__ w, int E) {
    int e = blockIdx.x * blockDim.x + threadIdx.x;
    if (e < E) {
        atomicAdd(&g_W1[src[e] * N_ASS + (dst[e] - ASS0)], w[e]);
    }
}

// ---------------------------------------------------------------------------
// Kernel 3: scatter hop-2 edges into dense W2 — ONLY edges that reach an
// output neuron (dst >= OUT0). Edges to associative dsts cannot affect the
// result (acc2 at associative neurons is never read).
// ---------------------------------------------------------------------------
__global__ void scatter2_kernel(const int* __restrict__ src,
                                const int* __restrict__ dst,
                                const float* __restrict__ w, int E) {
    int e = blockIdx.x * blockDim.x + threadIdx.x;
    if (e < E) {
        int d = dst[e];
        if (d >= OUT0) {
            atomicAdd(&g_W2[(src[e] - ASS0) * OUT_F + (d - OUT0)], w[e]);
        }
    }
}

// ---------------------------------------------------------------------------
// Tiled fp32 GEMM body: C[M,N] (+)= A[M,K_this] * B[K,N] over K range
// [blockIdx.z*KPER, +KPER). BM=BN=BK=64, 256 threads, 4x4 micro-tile/thread.
// ---------------------------------------------------------------------------
template<int M, int N, int K, int KPER, bool ATOMIC>
__device__ __forceinline__ void gemm_body(const float* __restrict__ A,
                                          const float* __restrict__ B,
                                          float* __restrict__ C) {
    constexpr int BM = 64, BN = 64, BK = 64;
    __shared__ float As[BK][BM + 4];  // As[k][m], +4 pad keeps float4 alignment
    __shared__ float Bs[BK][BN + 4];  // Bs[k][n]

    const int tid = threadIdx.x;
    const int tx  = tid & 15;         // 0..15 -> n direction
    const int ty  = tid >> 4;         // 0..15 -> m direction
    const int m0  = blockIdx.y * BM;
    const int n0  = blockIdx.x * BN;
    const int k0  = blockIdx.z * KPER;

    const int lr = tid >> 4;          // load row base  (0..15)
    const int lc = (tid & 15) * 4;    // load col base  (0..60)

    float acc[4][4] = {};

    for (int kt = 0; kt < KPER; kt += BK) {
        // Cooperative load: 4 float4 per thread from A (stored transposed)
        // and 4 float4 per thread from B (stored direct).
        #pragma unroll
        for (int i = 0; i < 4; i++) {
            int r = lr + i * 16;  // 0..63
            float4 av = *reinterpret_cast<const float4*>(
                A + (size_t)(m0 + r) * K + (k0 + kt + lc));
            As[lc + 0][r] = av.x;
            As[lc + 1][r] = av.y;
            As[lc + 2][r] = av.z;
            As[lc + 3][r] = av.w;
            float4 bv = *reinterpret_cast<const float4*>(
                B + (size_t)(k0 + kt + r) * N + (n0 + lc));
            *reinterpret_cast<float4*>(&Bs[r][lc]) = bv;
        }
        __syncthreads();

        #pragma unroll
        for (int k = 0; k < BK; k++) {
            float4 a = *reinterpret_cast<const float4*>(&As[k][ty * 4]);
            float4 b = *reinterpret_cast<const float4*>(&Bs[k][tx * 4]);
            acc[0][0] += a.x * b.x; acc[0][1] += a.x * b.y;
            acc[0][2] += a.x * b.z; acc[0][3] += a.x * b.w;
            acc[1][0] += a.y * b.x; acc[1][1] += a.y * b.y;
            acc[1][2] += a.y * b.z; acc[1][3] += a.y * b.w;
            acc[2][0] += a.z * b.x; acc[2][1] += a.z * b.y;
            acc[2][2] += a.z * b.z; acc[2][3] += a.z * b.w;
            acc[3][0] += a.w * b.x; acc[3][1] += a.w * b.y;
            acc[3][2] += a.w * b.z; acc[3][3] += a.w * b.w;
        }
        __syncthreads();
    }

    #pragma unroll
    for (int i = 0; i < 4; i++) {
        #pragma unroll
        for (int j = 0; j < 4; j++) {
            int r = m0 + ty * 4 + i;
            int c = n0 + tx * 4 + j;
            if (ATOMIC) atomicAdd(&C[(size_t)r * N + c], acc[i][j]);
            else        C[(size_t)r * N + c] = acc[i][j];
        }
    }
}

// GEMM1: H[128,4096] = x[128,256] @ W1[256,4096]   grid (64, 2, 1)
__global__ void __launch_bounds__(256)
gemm1_kernel(const float* __restrict__ x) {
    gemm_body<BATCH, N_ASS, IN_F, IN_F, false>(x, g_W1, g_H);
}

// GEMM2: out[128,256] += H[128,4096] @ W2[4096,256] split-K=16, grid (4, 2, 16)
__global__ void __launch_bounds__(256)
gemm2_kernel(float* __restrict__ out) {
    gemm_body<BATCH, OUT_F, N_ASS, 256, true>(g_H, g_W2, out);
}

// ---------------------------------------------------------------------------
// Launch
// ---------------------------------------------------------------------------
extern "C" void kernel_launch(void* const* d_in, const int* in_sizes, int n_in,
                              void* d_out, int out_size) {
    const float* x       = (const float*)d_in[0];  // [128, 256]
    const float* w_in    = (const float*)d_in[1];  // [E_in]
    const float* w_ass   = (const float*)d_in[2];  // [E_ass]
    const int*   in_src  = (const int*)  d_in[3];
    const int*   in_dst  = (const int*)  d_in[4];
    const int*   ass_src = (const int*)  d_in[5];
    const int*   ass_dst = (const int*)  d_in[6];

    const int E_in  = in_sizes[1];
    const int E_ass = in_sizes[2];
    float* out = (float*)d_out;

    zero_kernel<<<256, 256>>>(out);
    scatter1_kernel<<<(E_in  + 255) / 256, 256>>>(in_src,  in_dst,  w_in,  E_in);
    scatter2_kernel<<<(E_ass + 255) / 256, 256>>>(ass_src, ass_dst, w_ass, E_ass);
    gemm1_kernel<<<dim3(N_ASS / 64, BATCH / 64, 1), 256>>>(x);
    gemm2_kernel<<<dim3(OUT_F / 64, BATCH / 64, 16), 256>>>(out);
}